// round 16
// baseline (speedup 1.0000x reference)
#include <cuda_runtime.h>
#include <cuda_fp16.h>
#include <cuda_bf16.h>
#include <mma.h>
#include <math.h>

using namespace nvcuda;

// ----------------------------------------------------------------------------
// Static scratch (no cudaMalloc allowed).
// ----------------------------------------------------------------------------
__device__ float g_buf[184000000];

#define INV_AVG 0.0625f
#define INV_SQRT_DH 0.1767766952966369f
#define TBL_ROWS 4097
#define TBL_SCALE 819.2f

// packed fp32x2 helpers
__device__ __forceinline__ unsigned long long pack2(float lo, float hi) {
    unsigned long long r;
    asm("mov.b64 %0, {%1, %2};" : "=l"(r) : "f"(lo), "f"(hi));
    return r;
}
__device__ __forceinline__ void fma2(unsigned long long& d, unsigned long long a,
                                     unsigned long long b) {
    asm("fma.rn.f32x2 %0, %1, %2, %0;" : "+l"(d) : "l"(a), "l"(b));
}
__device__ __forceinline__ void unpack2(unsigned long long v, float& lo, float& hi) {
    asm("mov.b64 {%0, %1}, %2;" : "=f"(lo), "=f"(hi) : "l"(v));
}
__device__ __forceinline__ void red_add_v4(float* addr, float a, float b,
                                           float c, float d) {
    asm volatile("red.global.add.v4.f32 [%0], {%1, %2, %3, %4};"
                 :: "l"(addr), "f"(a), "f"(b), "f"(c), "f"(d) : "memory");
}

// ============================================================================
// wmma bf16 hi/lo-split GEMM: C[M,Ncols] (+=) A[M,128] @ W[128,Ncols].
// A' chunks: [Ahi, Ahi, Alo]; B' chunks: [Bhi, Blo, Bhi]  (lo*lo dropped).
// B stored [128][Ncols] row-major bf16 (same layout as fp32 weights).
// Block: 256 thr = 8 warps; warp tile 32x64; CTA tile 128x128.
// M buffers padded to multiples of 128 rows (no guards needed).
// ============================================================================
template<bool ACC>
__global__ void __launch_bounds__(256)
wgemm(const __nv_bfloat16* __restrict__ Ahi, const __nv_bfloat16* __restrict__ Alo,
      const __nv_bfloat16* __restrict__ Bhi, const __nv_bfloat16* __restrict__ Blo,
      float* __restrict__ C, int ldc, int Ncols)
{
    int w = threadIdx.x >> 5;
    int warp_m = w >> 1, warp_n = w & 1;
    int row0 = blockIdx.x * 128 + warp_m * 32;
    int col0 = blockIdx.y * 128 + warp_n * 64;

    wmma::fragment<wmma::accumulator, 16, 16, 16, float> acc[2][4];
#pragma unroll
    for (int m = 0; m < 2; m++)
#pragma unroll
        for (int n = 0; n < 4; n++) wmma::fill_fragment(acc[m][n], 0.0f);

#pragma unroll 1
    for (int kt = 0; kt < 24; kt++) {
        int chunk = kt >> 3;
        int kc = (kt & 7) * 16;
        const __nv_bfloat16* As = (chunk < 2) ? Ahi : Alo;
        const __nv_bfloat16* Bs = (chunk == 1) ? Blo : Bhi;
        wmma::fragment<wmma::matrix_a, 16, 16, 16, __nv_bfloat16, wmma::row_major> af[2];
        wmma::load_matrix_sync(af[0], As + (size_t)row0 * 128 + kc, 128);
        wmma::load_matrix_sync(af[1], As + (size_t)(row0 + 16) * 128 + kc, 128);
#pragma unroll
        for (int n = 0; n < 4; n++) {
            wmma::fragment<wmma::matrix_b, 16, 16, 16, __nv_bfloat16, wmma::row_major> bf;
            wmma::load_matrix_sync(bf, Bs + (size_t)kc * Ncols + col0 + n * 16, Ncols);
            wmma::mma_sync(acc[0][n], af[0], bf, acc[0][n]);
            wmma::mma_sync(acc[1][n], af[1], bf, acc[1][n]);
        }
    }
#pragma unroll
    for (int m = 0; m < 2; m++)
#pragma unroll
        for (int n = 0; n < 4; n++) {
            float* dst = C + (size_t)(row0 + m * 16) * ldc + col0 + n * 16;
            if (ACC) {
                wmma::fragment<wmma::accumulator, 16, 16, 16, float> cf;
                wmma::load_matrix_sync(cf, dst, ldc, wmma::mem_row_major);
#pragma unroll
                for (int i = 0; i < cf.num_elements; i++) acc[m][n].x[i] += cf.x[i];
            }
            wmma::store_matrix_sync(dst, acc[m][n], ldc, wmma::mem_row_major);
        }
}

// fp32 -> bf16 hi/lo split
__global__ void k_cvt(const float* __restrict__ x, __nv_bfloat16* __restrict__ hi,
                      __nv_bfloat16* __restrict__ lo, int total)
{
    int i = blockIdx.x * blockDim.x + threadIdx.x;
    if (i >= total) return;
    float v = x[i];
    __nv_bfloat16 h = __float2bfloat16(v);
    hi[i] = h;
    lo[i] = __float2bfloat16(v - __bfloat162float(h));
}

// weight pack (same layout, bf16 hi/lo): W[128][Ncols] row-major
__global__ void k_packb(const float* __restrict__ W, int total,
                        __nv_bfloat16* __restrict__ bhi, __nv_bfloat16* __restrict__ blo)
{
    int i = blockIdx.x * blockDim.x + threadIdx.x;
    if (i >= total) return;
    float v = W[i];
    __nv_bfloat16 h = __float2bfloat16(v);
    bhi[i] = h;
    blo[i] = __float2bfloat16(v - __bfloat162float(h));
}

// ============================================================================
// Edge geometry
// ============================================================================
__global__ void k_geom(const float* __restrict__ pos,
                       const int* __restrict__ snd, const int* __restrict__ rcv,
                       float* __restrict__ Y, float* __restrict__ C,
                       float* __restrict__ rad, float* __restrict__ ev, int E)
{
    int e = blockIdx.x * blockDim.x + threadIdx.x;
    if (e >= E) return;
    int s = snd[e], d = rcv[e];
    float vx = pos[d*3+0] - pos[s*3+0];
    float vy = pos[d*3+1] - pos[s*3+1];
    float vz = pos[d*3+2] - pos[s*3+2];
    float r = sqrtf(vx*vx + vy*vy + vz*vz);
    rad[e] = r;
    float inv = 1.0f / fmaxf(r, 1e-9f);
    float x = vx*inv, y = vy*inv, z = vz*inv;
    float x2 = x*x, y2 = y*y, z2 = z*z;
    const float s3 = 1.7320508075688772f, s5 = 2.2360679774997896f;
    const float s15 = 3.872983346207417f, s70 = 8.366600265340756f;
    const float s105 = 10.246950765959598f, s42 = 6.48074069840786f;
    const float s7 = 2.6457513110645907f;
    float Yl[16];
    Yl[0]  = 1.0f;
    Yl[1]  = s3*x;  Yl[2] = s3*y;  Yl[3] = s3*z;
    Yl[4]  = s15*x*y; Yl[5] = s15*y*z; Yl[6] = 0.5f*s5*(3.0f*z2 - 1.0f);
    Yl[7]  = s15*x*z; Yl[8] = 0.5f*s15*(x2 - y2);
    Yl[9]  = 0.25f*s70*y*(3.0f*x2 - y2);
    Yl[10] = s105*x*y*z;
    Yl[11] = 0.25f*s42*y*(5.0f*z2 - 1.0f);
    Yl[12] = 0.5f*s7*z*(5.0f*z2 - 3.0f);
    Yl[13] = 0.25f*s42*x*(5.0f*z2 - 1.0f);
    Yl[14] = 0.5f*s105*z*(x2 - y2);
    Yl[15] = 0.25f*s70*x*(x2 - 3.0f*y2);
    float Cc = (r < 5.0f) ? 0.5f*(cosf(0.6283185307179587f*r) + 1.0f) : 0.0f;
    C[e] = Cc;
    size_t yb = (size_t)e * 16;
    float sc = Cc * INV_AVG;
#pragma unroll
    for (int i = 0; i < 16; i++) Y[yb + i] = Yl[i];
    float* evd = ev + (size_t)d * 16;
#pragma unroll
    for (int i = 0; i < 16; i += 4)
        red_add_v4(evd + i, Yl[i]*sc, Yl[i+1]*sc, Yl[i+2]*sc, Yl[i+3]*sc);
}

__global__ void k_tablegrid(float* __restrict__ Rg)
{
    int idx = blockIdx.x * blockDim.x + threadIdx.x;
    if (idx >= TBL_ROWS * 32) return;
    int i = idx >> 5, kk = idx & 31;
    float r = (float)i * (5.0f / 4096.0f);
    float mu = 5.0f * (float)kk / 31.0f;
    float t = r - mu;
    Rg[idx] = __expf(-40.96f * t * t);
}

__global__ void k_embed(const int* __restrict__ species,
                        const float* __restrict__ embed,
                        float* __restrict__ f, int N)
{
    int idx = blockIdx.x * blockDim.x + threadIdx.x;
    if (idx >= N * 128) return;
    int n = idx >> 7, j = idx & 127;
    f[idx] = embed[species[n] * 128 + j];
}

__global__ void k_evinv(const float* __restrict__ ev, float* __restrict__ evi, int N)
{
    int idx = blockIdx.x * blockDim.x + threadIdx.x;
    if (idx >= N * 4) return;
    int n = idx >> 2, l = idx & 3;
    int st = (l == 0) ? 0 : (l == 1) ? 1 : (l == 2) ? 4 : 9;
    int en = (l == 0) ? 1 : (l == 1) ? 4 : (l == 2) ? 9 : 16;
    float sum = 0.0f;
    for (int c = st; c < en; c++) {
        float e = ev[n * 16 + c];
        sum += e * e;
    }
    evi[idx] = sum;
}

__global__ void k_pack(const float* __restrict__ Wq, const float* __restrict__ Wk,
                       const float* __restrict__ Wv, const float* __restrict__ Wq2,
                       const float* __restrict__ Wk2, const float* __restrict__ Wrbf1,
                       float* __restrict__ pWQKV, float* __restrict__ pWQ2K2,
                       float* __restrict__ pWr1cat)
{
    int idx = blockIdx.x * blockDim.x + threadIdx.x;
    const int n1 = 3 * 128 * 384;
    const int n2 = 3 * 128 * 256;
    const int n3 = 32 * 384;
    if (idx < n1) {
        int t = idx / (128 * 384), rem = idx % (128 * 384);
        int row = rem / 384, col = rem % 384;
        const float* src = (col < 128) ? Wq : (col < 256) ? Wk : Wv;
        int c = col & 127;
        pWQKV[idx] = src[(size_t)t * 16384 + row * 128 + c];
    } else if (idx < n1 + n2) {
        int j = idx - n1;
        int t = j / (128 * 256), rem = j % (128 * 256);
        int row = rem / 256, col = rem % 256;
        const float* src = (col < 128) ? Wq2 : Wk2;
        int c = col & 127;
        pWQ2K2[j] = src[(size_t)t * 16384 + row * 128 + c];
    } else if (idx < n1 + n2 + n3) {
        int j = idx - n1 - n2;
        int row = j / 384, col = j % 384;
        int t = col / 128, c = col & 127;
        pWr1cat[j] = Wrbf1[(size_t)t * 32 * 128 + row * 128 + c];
    }
}

// ============================================================================
// fp32 SGEMM (tables + exchange block + readout). Proven (R14).
// ============================================================================
template<int ACT, bool ACC, bool HASBIAS, bool SPLITA, bool YB>
__global__ void __launch_bounds__(256, 2)
sgemm(const float* __restrict__ A, int lda,
      const float* __restrict__ A2,
      const float* __restrict__ B, int ldb,
      const float* __restrict__ bias,
      float* __restrict__ C, int ldc,
      float* __restrict__ evp,
      int M, int K, int Ncols)
{
    __shared__ float As[2][16][128];
    __shared__ float Bs[2][16][128];
    int tid = threadIdx.x;
    int row0 = blockIdx.x * 128;
    int col0 = blockIdx.y * 128;
    int tx = tid & 15, ty = tid >> 4;
    int mbase = ty * 8, nbase = tx * 8;

    int mA  = tid >> 1;
    int kA0 = (tid & 1) * 8;
    int kB  = tid >> 4;
    int nB0 = (tid & 15) * 8;

    float a_reg[8], b_reg[8];

    auto loadG = [&](int k0) {
        int gm = row0 + mA;
#pragma unroll
        for (int h = 0; h < 2; h++) {
            int gk = k0 + kA0 + h * 4;
            float4 v = make_float4(0.f, 0.f, 0.f, 0.f);
            if (gm < M) {
                if (!SPLITA) {
                    if (gk < K) v = *(const float4*)&A[(size_t)gm * lda + gk];
                } else {
                    if (gk < 128) v = *(const float4*)&A[(size_t)gm * lda + gk];
                    else if (gk == 128) v = *(const float4*)&A2[(size_t)gm * 4];
                }
            }
            a_reg[h*4+0] = v.x; a_reg[h*4+1] = v.y; a_reg[h*4+2] = v.z; a_reg[h*4+3] = v.w;
        }
        int gk = k0 + kB;
#pragma unroll
        for (int h = 0; h < 2; h++) {
            int gn = col0 + nB0 + h * 4;
            float4 v = make_float4(0.f, 0.f, 0.f, 0.f);
            if (gk < K && gn < Ncols) v = *(const float4*)&B[(size_t)gk * ldb + gn];
            b_reg[h*4+0] = v.x; b_reg[h*4+1] = v.y; b_reg[h*4+2] = v.z; b_reg[h*4+3] = v.w;
        }
    };
    auto stsT = [&](int s) {
#pragma unroll
        for (int j = 0; j < 8; j++) As[s][kA0 + j][mA] = a_reg[j];
        *(float4*)&Bs[s][kB][nB0]     = make_float4(b_reg[0], b_reg[1], b_reg[2], b_reg[3]);
        *(float4*)&Bs[s][kB][nB0 + 4] = make_float4(b_reg[4], b_reg[5], b_reg[6], b_reg[7]);
    };

    unsigned long long acc[4][8];
#pragma unroll
    for (int i = 0; i < 4; i++)
#pragma unroll
        for (int j = 0; j < 8; j++) acc[i][j] = 0ull;

    int ktiles = (K + 15) >> 4;
    loadG(0);
    stsT(0);
    __syncthreads();

    for (int kt = 0; kt < ktiles; kt++) {
        int s = kt & 1;
        if (kt + 1 < ktiles) loadG((kt + 1) << 4);
#pragma unroll
        for (int kk = 0; kk < 16; kk++) {
            ulonglong2 a01 = *(const ulonglong2*)&As[s][kk][mbase];
            ulonglong2 a23 = *(const ulonglong2*)&As[s][kk][mbase + 4];
            float4 b0 = *(const float4*)&Bs[s][kk][nbase];
            float4 b1 = *(const float4*)&Bs[s][kk][nbase + 4];
            unsigned long long aa[4] = {a01.x, a01.y, a23.x, a23.y};
            unsigned long long bd[8];
            bd[0] = pack2(b0.x, b0.x); bd[1] = pack2(b0.y, b0.y);
            bd[2] = pack2(b0.z, b0.z); bd[3] = pack2(b0.w, b0.w);
            bd[4] = pack2(b1.x, b1.x); bd[5] = pack2(b1.y, b1.y);
            bd[6] = pack2(b1.z, b1.z); bd[7] = pack2(b1.w, b1.w);
#pragma unroll
            for (int i = 0; i < 4; i++)
#pragma unroll
                for (int j = 0; j < 8; j++)
                    fma2(acc[i][j], aa[i], bd[j]);
        }
        if (kt + 1 < ktiles) stsT(s ^ 1);
        __syncthreads();
    }

#pragma unroll
    for (int ip = 0; ip < 4; ip++) {
#pragma unroll
        for (int j = 0; j < 8; j++) {
            float lo, hi;
            unpack2(acc[ip][j], lo, hi);
            int gn = col0 + nbase + j;
            if (gn >= Ncols) continue;
#pragma unroll
            for (int h = 0; h < 2; h++) {
                int gm = row0 + mbase + ip * 2 + h;
                if (gm >= M) continue;
                float v = h ? hi : lo;
                if (HASBIAS) v += bias[gn];
                if (ACT == 1) v = v / (1.0f + __expf(-v));
                if (YB) {
                    if (gn < 128) {
                        C[(size_t)gm * ldc + gn] += v;
                    } else {
                        int l = gn - 128;
                        int st = (l == 0) ? 0 : (l == 1) ? 1 : (l == 2) ? 4 : 9;
                        int en = (l == 0) ? 1 : (l == 1) ? 4 : (l == 2) ? 9 : 16;
                        for (int c = st; c < en; c++) {
                            float e = evp[(size_t)gm * 16 + c];
                            evp[(size_t)gm * 16 + c] = e + v * e;
                        }
                    }
                } else {
                    if (ACC) v += C[(size_t)gm * ldc + gn];
                    C[(size_t)gm * ldc + gn] = v;
                }
            }
        }
    }
}

// ============================================================================
// Edge attention kernels (R14, unchanged)
// ============================================================================
__global__ void edge_att1(const int* __restrict__ snd, const int* __restrict__ rcv,
                          const float* __restrict__ Wdeg,
                          const float* __restrict__ ev,
                          const float* __restrict__ C,
                          const float* __restrict__ rad,
                          const float* __restrict__ tbl,
                          const float* __restrict__ qkv,
                          __half* __restrict__ wh, float* __restrict__ agg, int E)
{
    __shared__ float sW[512];
    for (int i = threadIdx.x; i < 512; i += blockDim.x) sW[i] = Wdeg[i];
    __syncthreads();
    int gw = (blockIdx.x * blockDim.x + threadIdx.x) >> 5;
    int lane = threadIdx.x & 31;
    if (gw >= E) return;
    int s = snd[gw], d = rcv[gw];
    float Cc = C[gw];

    float pe = 0.0f;
    if (lane < 16) pe = ev[(size_t)s * 16 + lane] * ev[(size_t)d * 16 + lane];
    float dd0 = __shfl_sync(0xffffffffu, pe, 0);
    float dd1 = __shfl_sync(0xffffffffu, pe, 1) + __shfl_sync(0xffffffffu, pe, 2)
              + __shfl_sync(0xffffffffu, pe, 3);
    float dd2 = __shfl_sync(0xffffffffu, pe, 4) + __shfl_sync(0xffffffffu, pe, 5)
              + __shfl_sync(0xffffffffu, pe, 6) + __shfl_sync(0xffffffffu, pe, 7)
              + __shfl_sync(0xffffffffu, pe, 8);
    float dd3 = __shfl_sync(0xffffffffu, pe, 9) + __shfl_sync(0xffffffffu, pe, 10)
              + __shfl_sync(0xffffffffu, pe, 11) + __shfl_sync(0xffffffffu, pe, 12)
              + __shfl_sync(0xffffffffu, pe, 13) + __shfl_sync(0xffffffffu, pe, 14)
              + __shfl_sync(0xffffffffu, pe, 15);

    float u = fminf(rad[gw] * TBL_SCALE, 4095.999f);
    int i0 = (int)u;
    float fr = u - (float)i0;

    int j0 = lane << 2;
    const float* t0p = tbl + (size_t)i0 * 128 + j0;
    float4 t0 = *(const float4*)t0p;
    float4 t1 = *(const float4*)(t0p + 128);

    float4 w4;
    w4.x = t0.x + fr*(t1.x-t0.x) + dd0*sW[j0+0] + dd1*sW[128+j0+0] + dd2*sW[256+j0+0] + dd3*sW[384+j0+0];
    w4.y = t0.y + fr*(t1.y-t0.y) + dd0*sW[j0+1] + dd1*sW[128+j0+1] + dd2*sW[256+j0+1] + dd3*sW[384+j0+1];
    w4.z = t0.z + fr*(t1.z-t0.z) + dd0*sW[j0+2] + dd1*sW[128+j0+2] + dd2*sW[256+j0+2] + dd3*sW[384+j0+2];
    w4.w = t0.w + fr*(t1.w-t0.w) + dd0*sW[j0+3] + dd1*sW[128+j0+3] + dd2*sW[256+j0+3] + dd3*sW[384+j0+3];
    __half2* wdst = (__half2*)(wh + (size_t)gw * 128 + j0);
    wdst[0] = __floats2half2_rn(w4.x, w4.y);
    wdst[1] = __floats2half2_rn(w4.z, w4.w);

    float4 q4 = *(const float4*)(qkv + (size_t)d * 384 + j0);
    float4 k4 = *(const float4*)(qkv + (size_t)s * 384 + 128 + j0);
    float4 v4 = *(const float4*)(qkv + (size_t)s * 384 + 256 + j0);
    float p = q4.x*(w4.x*k4.x) + q4.y*(w4.y*k4.y) + q4.z*(w4.z*k4.z) + q4.w*(w4.w*k4.w);
    p += __shfl_xor_sync(0xffffffffu, p, 4);
    p += __shfl_xor_sync(0xffffffffu, p, 2);
    p += __shfl_xor_sync(0xffffffffu, p, 1);
    float alpha = p * INV_SQRT_DH * Cc * INV_AVG;
    red_add_v4(agg + (size_t)d * 128 + j0,
               alpha * v4.x, alpha * v4.y, alpha * v4.z, alpha * v4.w);
}

__global__ void edge_att2(const int* __restrict__ snd, const int* __restrict__ rcv,
                          const float* __restrict__ Y, const float* __restrict__ C,
                          const float* __restrict__ q2k2,
                          const __half* __restrict__ wh,
                          float* __restrict__ ev, int E)
{
    int gw = (blockIdx.x * blockDim.x + threadIdx.x) >> 5;
    int lane = threadIdx.x & 31;
    if (gw >= E) return;
    int s = snd[gw], d = rcv[gw];
    float Cc = C[gw];
    int j0 = lane << 2;
    const __half2* wsrc = (const __half2*)(wh + (size_t)gw * 128 + j0);
    float2 wl = __half22float2(wsrc[0]);
    float2 whp = __half22float2(wsrc[1]);
    float4 q4 = *(const float4*)(q2k2 + (size_t)d * 256 + j0);
    float4 k4 = *(const float4*)(q2k2 + (size_t)s * 256 + 128 + j0);
    float p = q4.x*(wl.x*k4.x) + q4.y*(wl.y*k4.y) + q4.z*(whp.x*k4.z) + q4.w*(whp.y*k4.w);
    p += __shfl_xor_sync(0xffffffffu, p, 4);
    p += __shfl_xor_sync(0xffffffffu, p, 2);
    p += __shfl_xor_sync(0xffffffffu, p, 1);
    float alpha = p * INV_SQRT_DH * Cc;
    float a0 = __shfl_sync(0xffffffffu, alpha, 0);
    float a1 = __shfl_sync(0xffffffffu, alpha, 8);
    float a2 = __shfl_sync(0xffffffffu, alpha, 16);
    float a3 = __shfl_sync(0xffffffffu, alpha, 24);
    if (lane < 4) {
        float4 y4 = *(const float4*)(Y + (size_t)gw * 16 + lane * 4);
        float c0, c1, c2, c3;
        if (lane == 0)      { c0 = a0; c1 = a1; c2 = a1; c3 = a1; }
        else if (lane == 1) { c0 = a2; c1 = a2; c2 = a2; c3 = a2; }
        else if (lane == 2) { c0 = a2; c1 = a3; c2 = a3; c3 = a3; }
        else                { c0 = a3; c1 = a3; c2 = a3; c3 = a3; }
        red_add_v4(ev + (size_t)d * 16 + lane * 4,
                   c0 * y4.x * INV_AVG, c1 * y4.y * INV_AVG,
                   c2 * y4.z * INV_AVG, c3 * y4.w * INV_AVG);
    }
}

__global__ void k_energy(const float* __restrict__ hidn, const float* __restrict__ Wo2,
                         const float* __restrict__ bo2, const int* __restrict__ batch,
                         float* __restrict__ out, int N)
{
    int gw = (blockIdx.x * blockDim.x + threadIdx.x) >> 5;
    int lane = threadIdx.x & 31;
    if (gw >= N) return;
    float p = 0.0f;
    for (int j = lane; j < 128; j += 32) p += hidn[(size_t)gw * 128 + j] * Wo2[j];
#pragma unroll
    for (int o = 16; o > 0; o >>= 1) p += __shfl_xor_sync(0xffffffffu, p, o);
    if (lane == 0) atomicAdd(&out[batch[gw]], p + bo2[0]);
}

// ============================================================================
// Host launcher
// ============================================================================
extern "C" void kernel_launch(void* const* d_in, const int* in_sizes, int n_in,
                              void* d_out, int out_size)
{
    const float* pos     = (const float*)d_in[0];
    const int*   species = (const int*)d_in[1];
    const int*   snd     = (const int*)d_in[2];
    const int*   rcv     = (const int*)d_in[3];
    const int*   batch   = (const int*)d_in[4];
    const float* embed   = (const float*)d_in[5];
    const float* Wq      = (const float*)d_in[6];
    const float* Wk      = (const float*)d_in[7];
    const float* Wv      = (const float*)d_in[8];
    const float* Wo      = (const float*)d_in[9];
    const float* Wrbf1   = (const float*)d_in[10];
    const float* brbf1   = (const float*)d_in[11];
    const float* Wrbf2   = (const float*)d_in[12];
    const float* Wdeg    = (const float*)d_in[13];
    const float* Wq2     = (const float*)d_in[14];
    const float* Wk2     = (const float*)d_in[15];
    const float* Wex1    = (const float*)d_in[16];
    const float* bex1    = (const float*)d_in[17];
    const float* Wex2    = (const float*)d_in[18];
    const float* bex2    = (const float*)d_in[19];
    const float* Wo1     = (const float*)d_in[20];
    const float* bo1     = (const float*)d_in[21];
    const float* Wo2     = (const float*)d_in[22];
    const float* bo2     = (const float*)d_in[23];

    int N = in_sizes[0] / 3;
    int E = in_sizes[2];
    int mt = (N + 127) / 128;
    int Npad = mt * 128;

    float* base = nullptr;
    cudaGetSymbolAddress((void**)&base, g_buf);
    size_t o = 0;
    float* pY     = base + o; o += (size_t)E * 16;
    float* pC     = base + o; o += (size_t)E;
    float* pRad   = base + o; o += (size_t)E;
    __half* pWh   = (__half*)(base + o); o += (size_t)E * 64;
    float* pF     = base + o; o += (size_t)Npad * 128;   // padded (wmma ACC target)
    float* pEV    = base + o; o += (size_t)N * 16;
    float* pEVI   = base + o; o += (size_t)N * 4;
    float* pQKV   = base + o; o += (size_t)Npad * 384;   // padded
    float* pQ2K2  = base + o; o += (size_t)Npad * 256;   // padded
    float* pAGG   = base + o; o += (size_t)Npad * 128;   // padded
    float* pHID   = base + o; o += (size_t)N * 128;
    float* pTG    = base + o; o += (size_t)TBL_ROWS * 32;
    float* pTMP   = base + o; o += (size_t)TBL_ROWS * 384;
    float* pTW    = base + o; o += (size_t)3 * TBL_ROWS * 128;
    float* pWQKVp = base + o; o += (size_t)3 * 128 * 384;
    float* pWQ2K2p= base + o; o += (size_t)3 * 128 * 256;
    float* pWr1c  = base + o; o += (size_t)32 * 384;
    // bf16 activation splits (padded rows; padding stays zero)
    __nv_bfloat16* pFhi = (__nv_bfloat16*)(base + o); o += (size_t)Npad * 64;
    __nv_bfloat16* pFlo = (__nv_bfloat16*)(base + o); o += (size_t)Npad * 64;
    __nv_bfloat16* pAhi = (__nv_bfloat16*)(base + o); o += (size_t)Npad * 64;
    __nv_bfloat16* pAlo = (__nv_bfloat16*)(base + o); o += (size_t)Npad * 64;
    // bf16 weight packs [128][Ncols] row-major hi/lo
    __nv_bfloat16* pBQhi = (__nv_bfloat16*)(base + o); o += (size_t)3 * 128 * 192;
    __nv_bfloat16* pBQlo = (__nv_bfloat16*)(base + o); o += (size_t)3 * 128 * 192;
    __nv_bfloat16* pBOhi = (__nv_bfloat16*)(base + o); o += (size_t)3 * 128 * 64;
    __nv_bfloat16* pBOlo = (__nv_bfloat16*)(base + o); o += (size_t)3 * 128 * 64;
    __nv_bfloat16* pB2hi = (__nv_bfloat16*)(base + o); o += (size_t)3 * 128 * 128;
    __nv_bfloat16* pB2lo = (__nv_bfloat16*)(base + o); o += (size_t)3 * 128 * 128;

    cudaMemsetAsync(d_out, 0, (size_t)out_size * sizeof(float), 0);
    cudaMemsetAsync(pEV, 0, (size_t)N * 16 * sizeof(float), 0);

    {
        int packTot = 3*128*384 + 3*128*256 + 32*384;
        k_pack<<<(packTot + 255) / 256, 256>>>(Wq, Wk, Wv, Wq2, Wk2, Wrbf1,
                                               pWQKVp, pWQ2K2p, pWr1c);
    }
    k_geom<<<(E + 255) / 256, 256>>>(pos, snd, rcv, pY, pC, pRad, pEV, E);
    k_embed<<<(N * 128 + 255) / 256, 256>>>(species, embed, pF, N);

    // bf16 weight packs (layouts already [128][Ncols] row-major)
    k_packb<<<(3*128*384 + 255)/256, 256>>>(pWQKVp, 3*128*384, pBQhi, pBQlo);
    k_packb<<<(3*128*128 + 255)/256, 256>>>(Wo, 3*128*128, pBOhi, pBOlo);
    k_packb<<<(3*128*256 + 255)/256, 256>>>(pWQ2K2p, 3*128*256, pB2hi, pB2lo);

    // Radial tables
    k_tablegrid<<<(TBL_ROWS * 32 + 255) / 256, 256>>>(pTG);
    dim3 gT1((TBL_ROWS + 127) / 128, 3);
    sgemm<1, false, true, false, false><<<gT1, 256>>>(pTG, 32, nullptr, pWr1c, 384, brbf1,
                                                      pTMP, 384, nullptr, TBL_ROWS, 32, 384);
    dim3 gT((TBL_ROWS + 127) / 128, 1);
    for (int t = 0; t < 3; t++) {
        const float* Wrbf2_t = Wrbf2 + (size_t)t * 128 * 128;
        sgemm<0, false, false, false, false><<<gT, 256>>>(pTMP + t * 128, 384, nullptr,
                                                          Wrbf2_t, 128, nullptr,
                                                          pTW + (size_t)t * TBL_ROWS * 128, 128,
                                                          nullptr, TBL_ROWS, 128, 128);
    }

    dim3 gN128(mt, 1);
    int edgeBlocks = (E * 32 + 255) / 256;

    for (int t = 0; t < 3; t++) {
        const float* Wdeg_t  = Wdeg  + (size_t)t * 4 * 128;
        const float* Wex1_t  = Wex1  + (size_t)t * 132 * 128;
        const float* bex1_t  = bex1  + (size_t)t * 128;
        const float* Wex2_t  = Wex2  + (size_t)t * 128 * 132;
        const float* bex2_t  = bex2  + (size_t)t * 132;
        const float* TW_t    = pTW   + (size_t)t * TBL_ROWS * 128;

        // q|k|v via wmma bf16 hi/lo split
        k_cvt<<<(N*128 + 255)/256, 256>>>(pF, pFhi, pFlo, N * 128);
        wgemm<false><<<dim3(mt, 3), 256>>>(pFhi, pFlo,
            pBQhi + (size_t)t*128*384, pBQlo + (size_t)t*128*384, pQKV, 384, 384);
        // branch 1 attention
        cudaMemsetAsync(pAGG, 0, (size_t)N * 128 * sizeof(float), 0);
        edge_att1<<<edgeBlocks, 256>>>(snd, rcv, Wdeg_t, pEV, pC, pRad, TW_t, pQKV, pWh, pAGG, E);
        // f += agg @ Wo via wmma ACC
        k_cvt<<<(N*128 + 255)/256, 256>>>(pAGG, pAhi, pAlo, N * 128);
        wgemm<true><<<dim3(mt, 1), 256>>>(pAhi, pAlo,
            pBOhi + (size_t)t*128*128, pBOlo + (size_t)t*128*128, pF, 128, 128);
        // q2|k2 via wmma (uses updated f)
        k_cvt<<<(N*128 + 255)/256, 256>>>(pF, pFhi, pFlo, N * 128);
        wgemm<false><<<dim3(mt, 2), 256>>>(pFhi, pFlo,
            pB2hi + (size_t)t*128*256, pB2lo + (size_t)t*128*256, pQ2K2, 256, 256);
        edge_att2<<<edgeBlocks, 256>>>(snd, rcv, pY, pC, pQ2K2, pWh, pEV, E);
        // exchange block (fp32 sgemm, proven)
        k_evinv<<<(N * 4 + 255) / 256, 256>>>(pEV, pEVI, N);
        sgemm<1, false, true, true, false><<<gN128, 256>>>(pF, 128, pEVI, Wex1_t, 128, bex1_t,
                                                           pHID, 128, nullptr, N, 132, 128);
        dim3 gN132(mt, 2);
        sgemm<0, false, true, false, true><<<gN132, 256>>>(pHID, 128, nullptr, Wex2_t, 132, bex2_t,
                                                           pF, 128, pEV, N, 128, 132);
    }

    // readout
    sgemm<1, false, true, false, false><<<gN128, 256>>>(pF, 128, nullptr, Wo1, 128, bo1,
                                                        pHID, 128, nullptr, N, 128, 128);
    k_energy<<<(N * 32 + 255) / 256, 256>>>(pHID, Wo2, bo2, batch, (float*)d_out, N);
}

// round 17
// speedup vs baseline: 1.2843x; 1.2843x over previous
#include <cuda_runtime.h>
#include <cuda_fp16.h>
#include <cuda_bf16.h>
#include <mma.h>
#include <math.h>

using namespace nvcuda;

// ----------------------------------------------------------------------------
// Static scratch (no cudaMalloc allowed). Zero-initialized at module load.
// ----------------------------------------------------------------------------
__device__ float g_buf[184000000];

#define INV_AVG 0.0625f
#define INV_SQRT_DH 0.1767766952966369f
#define TBL_ROWS 4097
#define TBL_SCALE 819.2f

// packed fp32x2 helpers
__device__ __forceinline__ unsigned long long pack2(float lo, float hi) {
    unsigned long long r;
    asm("mov.b64 %0, {%1, %2};" : "=l"(r) : "f"(lo), "f"(hi));
    return r;
}
__device__ __forceinline__ void fma2(unsigned long long& d, unsigned long long a,
                                     unsigned long long b) {
    asm("fma.rn.f32x2 %0, %1, %2, %0;" : "+l"(d) : "l"(a), "l"(b));
}
__device__ __forceinline__ void unpack2(unsigned long long v, float& lo, float& hi) {
    asm("mov.b64 {%0, %1}, %2;" : "=f"(lo), "=f"(hi) : "l"(v));
}
__device__ __forceinline__ void red_add_v4(float* addr, float a, float b,
                                           float c, float d) {
    asm volatile("red.global.add.v4.f32 [%0], {%1, %2, %3, %4};"
                 :: "l"(addr), "f"(a), "f"(b), "f"(c), "f"(d) : "memory");
}

// ============================================================================
// wmma bf16 hi/lo-split GEMM, smem-staged:
//   C[M,Ncols] (+=) A[M,128] @ W[128,Ncols],  A fp32 (split in-register),
//   W pre-split bf16 hi/lo [128][Ncols] row-major.
// Per 16-k-tile: stage Ahi/Alo (col-major [k][m], ld 136) + Bhi/Blo
// (row-major [k][n], ld 136) in smem, then 3 passes: hi*hi + hi*lo + lo*hi.
// Block 256 = 8 warps; warp tile 32x64; CTA tile 128x128. M padded to 128.
// ============================================================================
template<bool ACC>
__global__ void __launch_bounds__(256)
wgemm(const float* __restrict__ A,
      const __nv_bfloat16* __restrict__ Bhi, const __nv_bfloat16* __restrict__ Blo,
      float* __restrict__ C, int ldc, int Ncols)
{
    __shared__ __nv_bfloat16 Ah[16 * 136], Al[16 * 136];
    __shared__ __nv_bfloat16 Bh[16 * 136], Bl[16 * 136];
    int tid = threadIdx.x;
    int w = tid >> 5;
    int warp_m = w >> 1, warp_n = w & 1;     // 4 x 2 warp grid
    int row0 = blockIdx.x * 128;
    int col0 = blockIdx.y * 128;

    wmma::fragment<wmma::accumulator, 16, 16, 16, float> acc[2][4];
#pragma unroll
    for (int m = 0; m < 2; m++)
#pragma unroll
        for (int n = 0; n < 4; n++) wmma::fill_fragment(acc[m][n], 0.0f);

    int am = tid >> 1, ak = (tid & 1) * 8;   // A: row 0..127, k-group 0/8
    int bk = tid >> 4, bn = (tid & 15) * 8;  // B: k-row 0..15, n-group

#pragma unroll 1
    for (int kt = 0; kt < 8; kt++) {
        int k0 = kt * 16;
        // stage A (fp32 -> bf16 hi/lo, col-major [k][m])
        const float* arow = A + (size_t)(row0 + am) * 128 + k0 + ak;
        float4 a0 = *(const float4*)arow;
        float4 a1 = *(const float4*)(arow + 4);
        float av[8] = {a0.x, a0.y, a0.z, a0.w, a1.x, a1.y, a1.z, a1.w};
#pragma unroll
        for (int j = 0; j < 8; j++) {
            float v = av[j];
            __nv_bfloat16 h = __float2bfloat16(v);
            Ah[(ak + j) * 136 + am] = h;
            Al[(ak + j) * 136 + am] = __float2bfloat16(v - __bfloat162float(h));
        }
        // stage B hi/lo (row-major [k][n])
        *(uint4*)&Bh[bk * 136 + bn] = *(const uint4*)&Bhi[(size_t)(k0 + bk) * Ncols + col0 + bn];
        *(uint4*)&Bl[bk * 136 + bn] = *(const uint4*)&Blo[(size_t)(k0 + bk) * Ncols + col0 + bn];
        __syncthreads();
#pragma unroll
        for (int pass = 0; pass < 3; pass++) {
            const __nv_bfloat16* As = (pass < 2) ? Ah : Al;
            const __nv_bfloat16* Bs = (pass == 1) ? Bl : Bh;
            wmma::fragment<wmma::matrix_a, 16, 16, 16, __nv_bfloat16, wmma::col_major> af[2];
            wmma::load_matrix_sync(af[0], As + warp_m * 32, 136);
            wmma::load_matrix_sync(af[1], As + warp_m * 32 + 16, 136);
#pragma unroll
            for (int n = 0; n < 4; n++) {
                wmma::fragment<wmma::matrix_b, 16, 16, 16, __nv_bfloat16, wmma::row_major> bf;
                wmma::load_matrix_sync(bf, Bs + warp_n * 64 + n * 16, 136);
                wmma::mma_sync(acc[0][n], af[0], bf, acc[0][n]);
                wmma::mma_sync(acc[1][n], af[1], bf, acc[1][n]);
            }
        }
        __syncthreads();
    }

    int rw0 = row0 + warp_m * 32;
    int cw0 = col0 + warp_n * 64;
#pragma unroll
    for (int m = 0; m < 2; m++)
#pragma unroll
        for (int n = 0; n < 4; n++) {
            float* dst = C + (size_t)(rw0 + m * 16) * ldc + cw0 + n * 16;
            if (ACC) {
                wmma::fragment<wmma::accumulator, 16, 16, 16, float> cf;
                wmma::load_matrix_sync(cf, dst, ldc, wmma::mem_row_major);
#pragma unroll
                for (int i = 0; i < cf.num_elements; i++) acc[m][n].x[i] += cf.x[i];
            }
            wmma::store_matrix_sync(dst, acc[m][n], ldc, wmma::mem_row_major);
        }
}

// weight pack: bf16 hi/lo, same [128][Ncols] row-major layout
__global__ void k_packb(const float* __restrict__ W, int total,
                        __nv_bfloat16* __restrict__ bhi, __nv_bfloat16* __restrict__ blo)
{
    int i = blockIdx.x * blockDim.x + threadIdx.x;
    if (i >= total) return;
    float v = W[i];
    __nv_bfloat16 h = __float2bfloat16(v);
    bhi[i] = h;
    blo[i] = __float2bfloat16(v - __bfloat162float(h));
}

// ============================================================================
// Edge geometry
// ============================================================================
__global__ void k_geom(const float* __restrict__ pos,
                       const int* __restrict__ snd, const int* __restrict__ rcv,
                       float* __restrict__ Y, float* __restrict__ C,
                       float* __restrict__ rad, float* __restrict__ ev, int E)
{
    int e = blockIdx.x * blockDim.x + threadIdx.x;
    if (e >= E) return;
    int s = snd[e], d = rcv[e];
    float vx = pos[d*3+0] - pos[s*3+0];
    float vy = pos[d*3+1] - pos[s*3+1];
    float vz = pos[d*3+2] - pos[s*3+2];
    float r = sqrtf(vx*vx + vy*vy + vz*vz);
    rad[e] = r;
    float inv = 1.0f / fmaxf(r, 1e-9f);
    float x = vx*inv, y = vy*inv, z = vz*inv;
    float x2 = x*x, y2 = y*y, z2 = z*z;
    const float s3 = 1.7320508075688772f, s5 = 2.2360679774997896f;
    const float s15 = 3.872983346207417f, s70 = 8.366600265340756f;
    const float s105 = 10.246950765959598f, s42 = 6.48074069840786f;
    const float s7 = 2.6457513110645907f;
    float Yl[16];
    Yl[0]  = 1.0f;
    Yl[1]  = s3*x;  Yl[2] = s3*y;  Yl[3] = s3*z;
    Yl[4]  = s15*x*y; Yl[5] = s15*y*z; Yl[6] = 0.5f*s5*(3.0f*z2 - 1.0f);
    Yl[7]  = s15*x*z; Yl[8] = 0.5f*s15*(x2 - y2);
    Yl[9]  = 0.25f*s70*y*(3.0f*x2 - y2);
    Yl[10] = s105*x*y*z;
    Yl[11] = 0.25f*s42*y*(5.0f*z2 - 1.0f);
    Yl[12] = 0.5f*s7*z*(5.0f*z2 - 3.0f);
    Yl[13] = 0.25f*s42*x*(5.0f*z2 - 1.0f);
    Yl[14] = 0.5f*s105*z*(x2 - y2);
    Yl[15] = 0.25f*s70*x*(x2 - 3.0f*y2);
    float Cc = (r < 5.0f) ? 0.5f*(cosf(0.6283185307179587f*r) + 1.0f) : 0.0f;
    C[e] = Cc;
    size_t yb = (size_t)e * 16;
    float sc = Cc * INV_AVG;
#pragma unroll
    for (int i = 0; i < 16; i++) Y[yb + i] = Yl[i];
    float* evd = ev + (size_t)d * 16;
#pragma unroll
    for (int i = 0; i < 16; i += 4)
        red_add_v4(evd + i, Yl[i]*sc, Yl[i+1]*sc, Yl[i+2]*sc, Yl[i+3]*sc);
}

__global__ void k_tablegrid(float* __restrict__ Rg)
{
    int idx = blockIdx.x * blockDim.x + threadIdx.x;
    if (idx >= TBL_ROWS * 32) return;
    int i = idx >> 5, kk = idx & 31;
    float r = (float)i * (5.0f / 4096.0f);
    float mu = 5.0f * (float)kk / 31.0f;
    float t = r - mu;
    Rg[idx] = __expf(-40.96f * t * t);
}

__global__ void k_embed(const int* __restrict__ species,
                        const float* __restrict__ embed,
                        float* __restrict__ f, int N)
{
    int idx = blockIdx.x * blockDim.x + threadIdx.x;
    if (idx >= N * 128) return;
    int n = idx >> 7, j = idx & 127;
    f[idx] = embed[species[n] * 128 + j];
}

__global__ void k_evinv(const float* __restrict__ ev, float* __restrict__ evi, int N)
{
    int idx = blockIdx.x * blockDim.x + threadIdx.x;
    if (idx >= N * 4) return;
    int n = idx >> 2, l = idx & 3;
    int st = (l == 0) ? 0 : (l == 1) ? 1 : (l == 2) ? 4 : 9;
    int en = (l == 0) ? 1 : (l == 1) ? 4 : (l == 2) ? 9 : 16;
    float sum = 0.0f;
    for (int c = st; c < en; c++) {
        float e = ev[n * 16 + c];
        sum += e * e;
    }
    evi[idx] = sum;
}

__global__ void k_pack(const float* __restrict__ Wq, const float* __restrict__ Wk,
                       const float* __restrict__ Wv, const float* __restrict__ Wq2,
                       const float* __restrict__ Wk2, const float* __restrict__ Wrbf1,
                       float* __restrict__ pWQKV, float* __restrict__ pWQ2K2,
                       float* __restrict__ pWr1cat)
{
    int idx = blockIdx.x * blockDim.x + threadIdx.x;
    const int n1 = 3 * 128 * 384;
    const int n2 = 3 * 128 * 256;
    const int n3 = 32 * 384;
    if (idx < n1) {
        int t = idx / (128 * 384), rem = idx % (128 * 384);
        int row = rem / 384, col = rem % 384;
        const float* src = (col < 128) ? Wq : (col < 256) ? Wk : Wv;
        int c = col & 127;
        pWQKV[idx] = src[(size_t)t * 16384 + row * 128 + c];
    } else if (idx < n1 + n2) {
        int j = idx - n1;
        int t = j / (128 * 256), rem = j % (128 * 256);
        int row = rem / 256, col = rem % 256;
        const float* src = (col < 128) ? Wq2 : Wk2;
        int c = col & 127;
        pWQ2K2[j] = src[(size_t)t * 16384 + row * 128 + c];
    } else if (idx < n1 + n2 + n3) {
        int j = idx - n1 - n2;
        int row = j / 384, col = j % 384;
        int t = col / 128, c = col & 127;
        pWr1cat[j] = Wrbf1[(size_t)t * 32 * 128 + row * 128 + c];
    }
}

// ============================================================================
// fp32 SGEMM (tables + exchange block + readout). Proven.
// ============================================================================
template<int ACT, bool ACC, bool HASBIAS, bool SPLITA, bool YB>
__global__ void __launch_bounds__(256, 2)
sgemm(const float* __restrict__ A, int lda,
      const float* __restrict__ A2,
      const float* __restrict__ B, int ldb,
      const float* __restrict__ bias,
      float* __restrict__ C, int ldc,
      float* __restrict__ evp,
      int M, int K, int Ncols)
{
    __shared__ float As[2][16][128];
    __shared__ float Bs[2][16][128];
    int tid = threadIdx.x;
    int row0 = blockIdx.x * 128;
    int col0 = blockIdx.y * 128;
    int tx = tid & 15, ty = tid >> 4;
    int mbase = ty * 8, nbase = tx * 8;

    int mA  = tid >> 1;
    int kA0 = (tid & 1) * 8;
    int kB  = tid >> 4;
    int nB0 = (tid & 15) * 8;

    float a_reg[8], b_reg[8];

    auto loadG = [&](int k0) {
        int gm = row0 + mA;
#pragma unroll
        for (int h = 0; h < 2; h++) {
            int gk = k0 + kA0 + h * 4;
            float4 v = make_float4(0.f, 0.f, 0.f, 0.f);
            if (gm < M) {
                if (!SPLITA) {
                    if (gk < K) v = *(const float4*)&A[(size_t)gm * lda + gk];
                } else {
                    if (gk < 128) v = *(const float4*)&A[(size_t)gm * lda + gk];
                    else if (gk == 128) v = *(const float4*)&A2[(size_t)gm * 4];
                }
            }
            a_reg[h*4+0] = v.x; a_reg[h*4+1] = v.y; a_reg[h*4+2] = v.z; a_reg[h*4+3] = v.w;
        }
        int gk = k0 + kB;
#pragma unroll
        for (int h = 0; h < 2; h++) {
            int gn = col0 + nB0 + h * 4;
            float4 v = make_float4(0.f, 0.f, 0.f, 0.f);
            if (gk < K && gn < Ncols) v = *(const float4*)&B[(size_t)gk * ldb + gn];
            b_reg[h*4+0] = v.x; b_reg[h*4+1] = v.y; b_reg[h*4+2] = v.z; b_reg[h*4+3] = v.w;
        }
    };
    auto stsT = [&](int s) {
#pragma unroll
        for (int j = 0; j < 8; j++) As[s][kA0 + j][mA] = a_reg[j];
        *(float4*)&Bs[s][kB][nB0]     = make_float4(b_reg[0], b_reg[1], b_reg[2], b_reg[3]);
        *(float4*)&Bs[s][kB][nB0 + 4] = make_float4(b_reg[4], b_reg[5], b_reg[6], b_reg[7]);
    };

    unsigned long long acc[4][8];
#pragma unroll
    for (int i = 0; i < 4; i++)
#pragma unroll
        for (int j = 0; j < 8; j++) acc[i][j] = 0ull;

    int ktiles = (K + 15) >> 4;
    loadG(0);
    stsT(0);
    __syncthreads();

    for (int kt = 0; kt < ktiles; kt++) {
        int s = kt & 1;
        if (kt + 1 < ktiles) loadG((kt + 1) << 4);
#pragma unroll
        for (int kk = 0; kk < 16; kk++) {
            ulonglong2 a01 = *(const ulonglong2*)&As[s][kk][mbase];
            ulonglong2 a23 = *(const ulonglong2*)&As[s][kk][mbase + 4];
            float4 b0 = *(const float4*)&Bs[s][kk][nbase];
            float4 b1 = *(const float4*)&Bs[s][kk][nbase + 4];
            unsigned long long aa[4] = {a01.x, a01.y, a23.x, a23.y};
            unsigned long long bd[8];
            bd[0] = pack2(b0.x, b0.x); bd[1] = pack2(b0.y, b0.y);
            bd[2] = pack2(b0.z, b0.z); bd[3] = pack2(b0.w, b0.w);
            bd[4] = pack2(b1.x, b1.x); bd[5] = pack2(b1.y, b1.y);
            bd[6] = pack2(b1.z, b1.z); bd[7] = pack2(b1.w, b1.w);
#pragma unroll
            for (int i = 0; i < 4; i++)
#pragma unroll
                for (int j = 0; j < 8; j++)
                    fma2(acc[i][j], aa[i], bd[j]);
        }
        if (kt + 1 < ktiles) stsT(s ^ 1);
        __syncthreads();
    }

#pragma unroll
    for (int ip = 0; ip < 4; ip++) {
#pragma unroll
        for (int j = 0; j < 8; j++) {
            float lo, hi;
            unpack2(acc[ip][j], lo, hi);
            int gn = col0 + nbase + j;
            if (gn >= Ncols) continue;
#pragma unroll
            for (int h = 0; h < 2; h++) {
                int gm = row0 + mbase + ip * 2 + h;
                if (gm >= M) continue;
                float v = h ? hi : lo;
                if (HASBIAS) v += bias[gn];
                if (ACT == 1) v = v / (1.0f + __expf(-v));
                if (YB) {
                    if (gn < 128) {
                        C[(size_t)gm * ldc + gn] += v;
                    } else {
                        int l = gn - 128;
                        int st = (l == 0) ? 0 : (l == 1) ? 1 : (l == 2) ? 4 : 9;
                        int en = (l == 0) ? 1 : (l == 1) ? 4 : (l == 2) ? 9 : 16;
                        for (int c = st; c < en; c++) {
                            float e = evp[(size_t)gm * 16 + c];
                            evp[(size_t)gm * 16 + c] = e + v * e;
                        }
                    }
                } else {
                    if (ACC) v += C[(size_t)gm * ldc + gn];
                    C[(size_t)gm * ldc + gn] = v;
                }
            }
        }
    }
}

// ============================================================================
// Edge attention kernels (unchanged)
// ============================================================================
__global__ void edge_att1(const int* __restrict__ snd, const int* __restrict__ rcv,
                          const float* __restrict__ Wdeg,
                          const float* __restrict__ ev,
                          const float* __restrict__ C,
                          const float* __restrict__ rad,
                          const float* __restrict__ tbl,
                          const float* __restrict__ qkv,
                          __half* __restrict__ wh, float* __restrict__ agg, int E)
{
    __shared__ float sW[512];
    for (int i = threadIdx.x; i < 512; i += blockDim.x) sW[i] = Wdeg[i];
    __syncthreads();
    int gw = (blockIdx.x * blockDim.x + threadIdx.x) >> 5;
    int lane = threadIdx.x & 31;
    if (gw >= E) return;
    int s = snd[gw], d = rcv[gw];
    float Cc = C[gw];

    float pe = 0.0f;
    if (lane < 16) pe = ev[(size_t)s * 16 + lane] * ev[(size_t)d * 16 + lane];
    float dd0 = __shfl_sync(0xffffffffu, pe, 0);
    float dd1 = __shfl_sync(0xffffffffu, pe, 1) + __shfl_sync(0xffffffffu, pe, 2)
              + __shfl_sync(0xffffffffu, pe, 3);
    float dd2 = __shfl_sync(0xffffffffu, pe, 4) + __shfl_sync(0xffffffffu, pe, 5)
              + __shfl_sync(0xffffffffu, pe, 6) + __shfl_sync(0xffffffffu, pe, 7)
              + __shfl_sync(0xffffffffu, pe, 8);
    float dd3 = __shfl_sync(0xffffffffu, pe, 9) + __shfl_sync(0xffffffffu, pe, 10)
              + __shfl_sync(0xffffffffu, pe, 11) + __shfl_sync(0xffffffffu, pe, 12)
              + __shfl_sync(0xffffffffu, pe, 13) + __shfl_sync(0xffffffffu, pe, 14)
              + __shfl_sync(0xffffffffu, pe, 15);

    float u = fminf(rad[gw] * TBL_SCALE, 4095.999f);
    int i0 = (int)u;
    float fr = u - (float)i0;

    int j0 = lane << 2;
    const float* t0p = tbl + (size_t)i0 * 128 + j0;
    float4 t0 = *(const float4*)t0p;
    float4 t1 = *(const float4*)(t0p + 128);

    float4 w4;
    w4.x = t0.x + fr*(t1.x-t0.x) + dd0*sW[j0+0] + dd1*sW[128+j0+0] + dd2*sW[256+j0+0] + dd3*sW[384+j0+0];
    w4.y = t0.y + fr*(t1.y-t0.y) + dd0*sW[j0+1] + dd1*sW[128+j0+1] + dd2*sW[256+j0+1] + dd3*sW[384+j0+1];
    w4.z = t0.z + fr*(t1.z-t0.z) + dd0*sW[j0+2] + dd1*sW[128+j0+2] + dd2*sW[256+j0+2] + dd3*sW[384+j0+2];
    w4.w = t0.w + fr*(t1.w-t0.w) + dd0*sW[j0+3] + dd1*sW[128+j0+3] + dd2*sW[256+j0+3] + dd3*sW[384+j0+3];
    __half2* wdst = (__half2*)(wh + (size_t)gw * 128 + j0);
    wdst[0] = __floats2half2_rn(w4.x, w4.y);
    wdst[1] = __floats2half2_rn(w4.z, w4.w);

    float4 q4 = *(const float4*)(qkv + (size_t)d * 384 + j0);
    float4 k4 = *(const float4*)(qkv + (size_t)s * 384 + 128 + j0);
    float4 v4 = *(const float4*)(qkv + (size_t)s * 384 + 256 + j0);
    float p = q4.x*(w4.x*k4.x) + q4.y*(w4.y*k4.y) + q4.z*(w4.z*k4.z) + q4.w*(w4.w*k4.w);
    p += __shfl_xor_sync(0xffffffffu, p, 4);
    p += __shfl_xor_sync(0xffffffffu, p, 2);
    p += __shfl_xor_sync(0xffffffffu, p, 1);
    float alpha = p * INV_SQRT_DH * Cc * INV_AVG;
    red_add_v4(agg + (size_t)d * 128 + j0,
               alpha * v4.x, alpha * v4.y, alpha * v4.z, alpha * v4.w);
}

__global__ void edge_att2(const int* __restrict__ snd, const int* __restrict__ rcv,
                          const float* __restrict__ Y, const float* __restrict__ C,
                          const float* __restrict__ q2k2,
                          const __half* __restrict__ wh,
                          float* __restrict__ ev, int E)
{
    int gw = (blockIdx.x * blockDim.x + threadIdx.x) >> 5;
    int lane = threadIdx.x & 31;
    if (gw >= E) return;
    int s = snd[gw], d = rcv[gw];
    float Cc = C[gw];
    int j0 = lane << 2;
    const __half2* wsrc = (const __half2*)(wh + (size_t)gw * 128 + j0);
    float2 wl = __half22float2(wsrc[0]);
    float2 whp = __half22float2(wsrc[1]);
    float4 q4 = *(const float4*)(q2k2 + (size_t)d * 256 + j0);
    float4 k4 = *(const float4*)(q2k2 + (size_t)s * 256 + 128 + j0);
    float p = q4.x*(wl.x*k4.x) + q4.y*(wl.y*k4.y) + q4.z*(whp.x*k4.z) + q4.w*(whp.y*k4.w);
    p += __shfl_xor_sync(0xffffffffu, p, 4);
    p += __shfl_xor_sync(0xffffffffu, p, 2);
    p += __shfl_xor_sync(0xffffffffu, p, 1);
    float alpha = p * INV_SQRT_DH * Cc;
    float a0 = __shfl_sync(0xffffffffu, alpha, 0);
    float a1 = __shfl_sync(0xffffffffu, alpha, 8);
    float a2 = __shfl_sync(0xffffffffu, alpha, 16);
    float a3 = __shfl_sync(0xffffffffu, alpha, 24);
    if (lane < 4) {
        float4 y4 = *(const float4*)(Y + (size_t)gw * 16 + lane * 4);
        float c0, c1, c2, c3;
        if (lane == 0)      { c0 = a0; c1 = a1; c2 = a1; c3 = a1; }
        else if (lane == 1) { c0 = a2; c1 = a2; c2 = a2; c3 = a2; }
        else if (lane == 2) { c0 = a2; c1 = a3; c2 = a3; c3 = a3; }
        else                { c0 = a3; c1 = a3; c2 = a3; c3 = a3; }
        red_add_v4(ev + (size_t)d * 16 + lane * 4,
                   c0 * y4.x * INV_AVG, c1 * y4.y * INV_AVG,
                   c2 * y4.z * INV_AVG, c3 * y4.w * INV_AVG);
    }
}

__global__ void k_energy(const float* __restrict__ hidn, const float* __restrict__ Wo2,
                         const float* __restrict__ bo2, const int* __restrict__ batch,
                         float* __restrict__ out, int N)
{
    int gw = (blockIdx.x * blockDim.x + threadIdx.x) >> 5;
    int lane = threadIdx.x & 31;
    if (gw >= N) return;
    float p = 0.0f;
    for (int j = lane; j < 128; j += 32) p += hidn[(size_t)gw * 128 + j] * Wo2[j];
#pragma unroll
    for (int o = 16; o > 0; o >>= 1) p += __shfl_xor_sync(0xffffffffu, p, o);
    if (lane == 0) atomicAdd(&out[batch[gw]], p + bo2[0]);
}

// ============================================================================
// Host launcher
// ============================================================================
extern "C" void kernel_launch(void* const* d_in, const int* in_sizes, int n_in,
                              void* d_out, int out_size)
{
    const float* pos     = (const float*)d_in[0];
    const int*   species = (const int*)d_in[1];
    const int*   snd     = (const int*)d_in[2];
    const int*   rcv     = (const int*)d_in[3];
    const int*   batch   = (const int*)d_in[4];
    const float* embed   = (const float*)d_in[5];
    const float* Wq      = (const float*)d_in[6];
    const float* Wk      = (const float*)d_in[7];
    const float* Wv      = (const float*)d_in[8];
    const float* Wo      = (const float*)d_in[9];
    const float* Wrbf1   = (const float*)d_in[10];
    const float* brbf1   = (const float*)d_in[11];
    const float* Wrbf2   = (const float*)d_in[12];
    const float* Wdeg    = (const float*)d_in[13];
    const float* Wq2     = (const float*)d_in[14];
    const float* Wk2     = (const float*)d_in[15];
    const float* Wex1    = (const float*)d_in[16];
    const float* bex1    = (const float*)d_in[17];
    const float* Wex2    = (const float*)d_in[18];
    const float* bex2    = (const float*)d_in[19];
    const float* Wo1     = (const float*)d_in[20];
    const float* bo1     = (const float*)d_in[21];
    const float* Wo2     = (const float*)d_in[22];
    const float* bo2     = (const float*)d_in[23];

    int N = in_sizes[0] / 3;
    int E = in_sizes[2];
    int mt = (N + 127) / 128;
    int Npad = mt * 128;

    float* base = nullptr;
    cudaGetSymbolAddress((void**)&base, g_buf);
    size_t o = 0;
    float* pY     = base + o; o += (size_t)E * 16;
    float* pC     = base + o; o += (size_t)E;
    float* pRad   = base + o; o += (size_t)E;
    __half* pWh   = (__half*)(base + o); o += (size_t)E * 64;
    float* pF     = base + o; o += (size_t)Npad * 128;   // padded (padding stays 0)
    float* pEV    = base + o; o += (size_t)N * 16;
    float* pEVI   = base + o; o += (size_t)N * 4;
    float* pQKV   = base + o; o += (size_t)Npad * 384;   // padded
    float* pQ2K2  = base + o; o += (size_t)Npad * 256;   // padded
    float* pAGG   = base + o; o += (size_t)Npad * 128;   // padded
    float* pHID   = base + o; o += (size_t)N * 128;
    float* pTG    = base + o; o += (size_t)TBL_ROWS * 32;
    float* pTMP   = base + o; o += (size_t)TBL_ROWS * 384;
    float* pTW    = base + o; o += (size_t)3 * TBL_ROWS * 128;
    float* pWQKVp = base + o; o += (size_t)3 * 128 * 384;
    float* pWQ2K2p= base + o; o += (size_t)3 * 128 * 256;
    float* pWr1c  = base + o; o += (size_t)32 * 384;
    // bf16 weight packs [128][Ncols] row-major hi/lo
    __nv_bfloat16* pBQhi = (__nv_bfloat16*)(base + o); o += (size_t)3 * 128 * 192;
    __nv_bfloat16* pBQlo = (__nv_bfloat16*)(base + o); o += (size_t)3 * 128 * 192;
    __nv_bfloat16* pBOhi = (__nv_bfloat16*)(base + o); o += (size_t)3 * 128 * 64;
    __nv_bfloat16* pBOlo = (__nv_bfloat16*)(base + o); o += (size_t)3 * 128 * 64;
    __nv_bfloat16* pB2hi = (__nv_bfloat16*)(base + o); o += (size_t)3 * 128 * 128;
    __nv_bfloat16* pB2lo = (__nv_bfloat16*)(base + o); o += (size_t)3 * 128 * 128;

    cudaMemsetAsync(d_out, 0, (size_t)out_size * sizeof(float), 0);
    cudaMemsetAsync(pEV, 0, (size_t)N * 16 * sizeof(float), 0);

    {
        int packTot = 3*128*384 + 3*128*256 + 32*384;
        k_pack<<<(packTot + 255) / 256, 256>>>(Wq, Wk, Wv, Wq2, Wk2, Wrbf1,
                                               pWQKVp, pWQ2K2p, pWr1c);
    }
    k_geom<<<(E + 255) / 256, 256>>>(pos, snd, rcv, pY, pC, pRad, pEV, E);
    k_embed<<<(N * 128 + 255) / 256, 256>>>(species, embed, pF, N);

    // bf16 weight packs
    k_packb<<<(3*128*384 + 255)/256, 256>>>(pWQKVp, 3*128*384, pBQhi, pBQlo);
    k_packb<<<(3*128*128 + 255)/256, 256>>>(Wo, 3*128*128, pBOhi, pBOlo);
    k_packb<<<(3*128*256 + 255)/256, 256>>>(pWQ2K2p, 3*128*256, pB2hi, pB2lo);

    // Radial tables
    k_tablegrid<<<(TBL_ROWS * 32 + 255) / 256, 256>>>(pTG);
    dim3 gT1((TBL_ROWS + 127) / 128, 3);
    sgemm<1, false, true, false, false><<<gT1, 256>>>(pTG, 32, nullptr, pWr1c, 384, brbf1,
                                                      pTMP, 384, nullptr, TBL_ROWS, 32, 384);
    dim3 gT((TBL_ROWS + 127) / 128, 1);
    for (int t = 0; t < 3; t++) {
        const float* Wrbf2_t = Wrbf2 + (size_t)t * 128 * 128;
        sgemm<0, false, false, false, false><<<gT, 256>>>(pTMP + t * 128, 384, nullptr,
                                                          Wrbf2_t, 128, nullptr,
                                                          pTW + (size_t)t * TBL_ROWS * 128, 128,
                                                          nullptr, TBL_ROWS, 128, 128);
    }

    dim3 gN128(mt, 1);
    int edgeBlocks = (E * 32 + 255) / 256;

    for (int t = 0; t < 3; t++) {
        const float* Wdeg_t  = Wdeg  + (size_t)t * 4 * 128;
        const float* Wex1_t  = Wex1  + (size_t)t * 132 * 128;
        const float* bex1_t  = bex1  + (size_t)t * 128;
        const float* Wex2_t  = Wex2  + (size_t)t * 128 * 132;
        const float* bex2_t  = bex2  + (size_t)t * 132;
        const float* TW_t    = pTW   + (size_t)t * TBL_ROWS * 128;

        // q|k|v via smem-staged wmma (fp32 A split in-kernel)
        wgemm<false><<<dim3(mt, 3), 256>>>(pF,
            pBQhi + (size_t)t*128*384, pBQlo + (size_t)t*128*384, pQKV, 384, 384);
        // branch 1 attention
        cudaMemsetAsync(pAGG, 0, (size_t)Npad * 128 * sizeof(float), 0);
        edge_att1<<<edgeBlocks, 256>>>(snd, rcv, Wdeg_t, pEV, pC, pRad, TW_t, pQKV, pWh, pAGG, E);
        // f += agg @ Wo via wmma ACC
        wgemm<true><<<dim3(mt, 1), 256>>>(pAGG,
            pBOhi + (size_t)t*128*128, pBOlo + (size_t)t*128*128, pF, 128, 128);
        // q2|k2 via wmma (uses updated f)
        wgemm<false><<<dim3(mt, 2), 256>>>(pF,
            pB2hi + (size_t)t*128*256, pB2lo + (size_t)t*128*256, pQ2K2, 256, 256);
        edge_att2<<<edgeBlocks, 256>>>(snd, rcv, pY, pC, pQ2K2, pWh, pEV, E);
        // exchange block (fp32 sgemm, proven)
        k_evinv<<<(N * 4 + 255) / 256, 256>>>(pEV, pEVI, N);
        sgemm<1, false, true, true, false><<<gN128, 256>>>(pF, 128, pEVI, Wex1_t, 128, bex1_t,
                                                           pHID, 128, nullptr, N, 132, 128);
        dim3 gN132(mt, 2);
        sgemm<0, false, true, false, true><<<gN132, 256>>>(pHID, 128, nullptr, Wex2_t, 132, bex2_t,
                                                           pF, 128, pEV, N, 128, 132);
    }

    // readout
    sgemm<1, false, true, false, false><<<gN128, 256>>>(pF, 128, nullptr, Wo1, 128, bo1,
                                                        pHID, 128, nullptr, N, 128, 128);
    k_energy<<<(N * 32 + 255) / 256, 256>>>(pHID, Wo2, bo2, batch, (float*)d_out, N);
}